// round 1
// baseline (speedup 1.0000x reference)
#include <cuda_runtime.h>
#include <cuda_bf16.h>

#define W 128
#define G 64
#define MAXN 100000
#define EPS 1e-5f

// ---------------- scratch (static device globals; no allocation) -------------
__device__ float g_xn[MAXN * W];
__device__ float g_agg[MAXN * W];
__device__ float g_h1[MAXN * W];
__device__ float g_sum[G * W];
__device__ float g_sumsq[G * W];
__device__ float g_alpha[G * W];
__device__ float g_beta[G * W];
__device__ float g_cnt[G];

// ---------------- 1. per-graph stats (batch_map is sorted) ------------------
// One block per 256-row chunk, 128 threads (one per feature). Run-length
// accumulate in registers; flush to global atomics only on graph change.
__global__ __launch_bounds__(128) void stats_kernel(
    const float* __restrict__ x, const int* __restrict__ bmap, int n, int chunk)
{
    int n0 = blockIdx.x * chunk;
    if (n0 >= n) return;
    int n1 = min(n0 + chunk, n);
    int f = threadIdx.x;

    float s = 0.f, ss = 0.f;
    int curg = bmap[n0];
    int runStart = n0;
    for (int r = n0; r < n1; r++) {
        int g = bmap[r];                       // uniform across block -> broadcast
        if (g != curg) {
            atomicAdd(&g_sum[curg * W + f], s);
            atomicAdd(&g_sumsq[curg * W + f], ss);
            if (f == 0) atomicAdd(&g_cnt[curg], (float)(r - runStart));
            s = 0.f; ss = 0.f; curg = g; runStart = r;
        }
        float v = x[(size_t)r * W + f];
        s += v; ss += v * v;
    }
    atomicAdd(&g_sum[curg * W + f], s);
    atomicAdd(&g_sumsq[curg * W + f], ss);
    if (f == 0) atomicAdd(&g_cnt[curg], (float)(n1 - runStart));
}

// ---------------- 2. finalize per-(graph,feature) affine --------------------
// xn = weight*(x - ms*mean)/std + bias  ==  alpha*x + beta
__global__ __launch_bounds__(128) void finalize_kernel(
    const float* __restrict__ gnw, const float* __restrict__ gnb,
    const float* __restrict__ msc)
{
    int g = blockIdx.x, f = threadIdx.x;
    float cnt  = g_cnt[g];
    float inv  = (cnt > 0.f) ? (1.f / cnt) : 0.f;
    float mean = g_sum[g * W + f] * inv;
    float q    = g_sumsq[g * W + f] * inv;
    float m    = msc[f];
    // var = E[(x-m*mean)^2] = E[x^2] - mean^2 * m * (2 - m)
    float var  = q - mean * mean * m * (2.f - m);
    float istd = rsqrtf(var + EPS);
    float a    = gnw[f] * istd;
    g_alpha[g * W + f] = a;
    g_beta[g * W + f]  = gnb[f] - a * m * mean;
}

// ---------------- 3. normalize + zero agg -----------------------------------
__global__ __launch_bounds__(128) void norm_kernel(
    const float* __restrict__ x, const int* __restrict__ bmap, int n)
{
    int r = blockIdx.x;
    if (r >= n) return;
    int f = threadIdx.x;
    int g = bmap[r];                            // uniform -> broadcast
    size_t i = (size_t)r * W + f;
    g_xn[i]  = g_alpha[g * W + f] * x[i] + g_beta[g * W + f];
    g_agg[i] = 0.f;
}

// ---------------- 4. edge scatter: agg[dst] += ew * in[src] -----------------
// One warp per edge: 32 threads x float4 = 512B coalesced gather + red.v4
__global__ __launch_bounds__(256) void scatter_kernel(
    const int* __restrict__ src, const int* __restrict__ dst,
    const float* __restrict__ ew, const float4* __restrict__ in,
    float* __restrict__ agg, int E)
{
    int idx = blockIdx.x * blockDim.x + threadIdx.x;
    int total = E * 32;
    if (idx >= total) return;
    int e = idx >> 5;
    int c = idx & 31;
    int s = __ldg(src + e);
    int d = __ldg(dst + e);
    float w = __ldg(ew + e);
    float4 v = __ldg(in + (size_t)s * 32 + c);
    float4 m; m.x = v.x * w; m.y = v.y * w; m.z = v.z * w; m.w = v.w * w;
    float* p = agg + (size_t)d * W + c * 4;
    asm volatile("red.global.add.v4.f32 [%0], {%1,%2,%3,%4};"
                 :: "l"(p), "f"(m.x), "f"(m.y), "f"(m.z), "f"(m.w) : "memory");
}

// ---------------- 5. fused dual-GEMM + epilogue -----------------------------
// out[r,:] = epilogue( A[r,:] @ Wrel^T + B[r,:] @ Wroot^T + brel )
// MODE 0: LeakyReLU(0.1)     MODE 1: + resid (residual add)
// Block: 256 threads, tile 64 rows x 128 outputs, thread = 4 rows x 8 outs.
template <int MODE>
__global__ __launch_bounds__(256) void gemm_kernel(
    const float* __restrict__ A, const float* __restrict__ B,
    const float* __restrict__ Wrel, const float* __restrict__ brel,
    const float* __restrict__ Wroot, const float* __restrict__ resid,
    float* __restrict__ out, int n)
{
    __shared__ float sW[32 * 132];   // transposed weight tile: sW[k][o], stride 132
    __shared__ float sIn[64 * 36];   // input tile: sIn[r][k], stride 36

    int tid = threadIdx.x;
    int tr  = tid >> 4;              // 0..15 -> rows tr*4..tr*4+3
    int tc  = tid & 15;              // 0..15 -> outputs tc*8..tc*8+7
    int r0  = blockIdx.x * 64;

    float acc[4][8];
    #pragma unroll
    for (int j = 0; j < 4; j++)
        #pragma unroll
        for (int m = 0; m < 8; m++) acc[j][m] = 0.f;

    #pragma unroll 1
    for (int pass = 0; pass < 2; pass++) {
        const float* In = pass ? B : A;
        const float* Wm = pass ? Wroot : Wrel;
        #pragma unroll 1
        for (int k0 = 0; k0 < W; k0 += 32) {
            __syncthreads();
            // weights: 32k x 128o = 4096 elems, transposed store
            #pragma unroll
            for (int it = 0; it < 16; it++) {
                int lin = tid + it * 256;
                int o = lin >> 5, kk = lin & 31;
                sW[kk * 132 + o] = Wm[o * W + k0 + kk];
            }
            // inputs: 64r x 32k = 2048 elems
            #pragma unroll
            for (int it = 0; it < 8; it++) {
                int lin = tid + it * 256;
                int rr = lin >> 5, kk = lin & 31;
                int r = r0 + rr;
                sIn[rr * 36 + kk] = (r < n) ? In[(size_t)r * W + k0 + kk] : 0.f;
            }
            __syncthreads();

            #pragma unroll
            for (int k = 0; k < 32; k += 4) {
                float areg[4][4];
                #pragma unroll
                for (int j = 0; j < 4; j++) {
                    float4 t = *(const float4*)&sIn[(tr * 4 + j) * 36 + k];
                    areg[j][0] = t.x; areg[j][1] = t.y; areg[j][2] = t.z; areg[j][3] = t.w;
                }
                #pragma unroll
                for (int kk = 0; kk < 4; kk++) {
                    float4 w0 = *(const float4*)&sW[(k + kk) * 132 + tc * 8];
                    float4 w1 = *(const float4*)&sW[(k + kk) * 132 + tc * 8 + 4];
                    float wv[8] = {w0.x, w0.y, w0.z, w0.w, w1.x, w1.y, w1.z, w1.w};
                    #pragma unroll
                    for (int j = 0; j < 4; j++)
                        #pragma unroll
                        for (int m = 0; m < 8; m++)
                            acc[j][m] = fmaf(areg[j][kk], wv[m], acc[j][m]);
                }
            }
        }
    }

    // epilogue
    float bv[8];
    #pragma unroll
    for (int m = 0; m < 8; m++) bv[m] = __ldg(brel + tc * 8 + m);

    #pragma unroll
    for (int j = 0; j < 4; j++) {
        int r = r0 + tr * 4 + j;
        if (r >= n) continue;
        float v[8];
        #pragma unroll
        for (int m = 0; m < 8; m++) {
            v[m] = acc[j][m] + bv[m];
            if (MODE == 0) v[m] = (v[m] >= 0.f) ? v[m] : 0.1f * v[m];
        }
        if (MODE == 1) {
            const float4* rp = (const float4*)(resid + (size_t)r * W + tc * 8);
            float4 r0v = __ldg(rp), r1v = __ldg(rp + 1);
            v[0] += r0v.x; v[1] += r0v.y; v[2] += r0v.z; v[3] += r0v.w;
            v[4] += r1v.x; v[5] += r1v.y; v[6] += r1v.z; v[7] += r1v.w;
        }
        float4* op = (float4*)(out + (size_t)r * W + tc * 8);
        op[0] = make_float4(v[0], v[1], v[2], v[3]);
        op[1] = make_float4(v[4], v[5], v[6], v[7]);
    }
}

// ---------------- launch -----------------------------------------------------
extern "C" void kernel_launch(void* const* d_in, const int* in_sizes, int n_in,
                              void* d_out, int out_size)
{
    const float* x      = (const float*)d_in[0];
    const int*   eidx   = (const int*)d_in[1];
    const float* ew     = (const float*)d_in[2];
    const int*   bmap   = (const int*)d_in[3];
    const float* gnw    = (const float*)d_in[4];
    const float* gnb    = (const float*)d_in[5];
    const float* msc    = (const float*)d_in[6];
    const float* Wrel1  = (const float*)d_in[7];
    const float* brel1  = (const float*)d_in[8];
    const float* Wroot1 = (const float*)d_in[9];
    const float* Wrel2  = (const float*)d_in[10];
    const float* brel2  = (const float*)d_in[11];
    const float* Wroot2 = (const float*)d_in[12];
    float* out = (float*)d_out;

    int n = in_sizes[0] / W;
    int E = in_sizes[2];
    const int* src = eidx;
    const int* dst = eidx + E;

    // symbol addresses (host API, not captured; no allocation)
    void *p_sum, *p_sumsq, *p_cnt, *p_xn, *p_agg, *p_h1;
    cudaGetSymbolAddress(&p_sum, g_sum);
    cudaGetSymbolAddress(&p_sumsq, g_sumsq);
    cudaGetSymbolAddress(&p_cnt, g_cnt);
    cudaGetSymbolAddress(&p_xn, g_xn);
    cudaGetSymbolAddress(&p_agg, g_agg);
    cudaGetSymbolAddress(&p_h1, g_h1);
    float* agg = (float*)p_agg;
    float* xn  = (float*)p_xn;
    float* h1  = (float*)p_h1;

    // zero stats accumulators
    cudaMemsetAsync(p_sum,   0, G * W * sizeof(float), 0);
    cudaMemsetAsync(p_sumsq, 0, G * W * sizeof(float), 0);
    cudaMemsetAsync(p_cnt,   0, G * sizeof(float), 0);

    // 1-2: GraphNorm stats + affine coefficients
    const int CHUNK = 256;
    int nblk = (n + CHUNK - 1) / CHUNK;
    stats_kernel<<<nblk, 128>>>(x, bmap, n, CHUNK);
    finalize_kernel<<<G, 128>>>(gnw, gnb, msc);

    // 3: normalize + zero agg
    norm_kernel<<<n, 128>>>(x, bmap, n);

    // 4: conv1 scatter
    int sThreads = 256;
    int sBlocks  = (E * 32 + sThreads - 1) / sThreads;
    scatter_kernel<<<sBlocks, sThreads>>>(src, dst, ew, (const float4*)xn, agg, E);

    // 5: conv1 GEMMs + bias + LeakyReLU -> h1
    int gBlocks = (n + 63) / 64;
    gemm_kernel<0><<<gBlocks, 256>>>(agg, xn, Wrel1, brel1, Wroot1, nullptr, h1, n);

    // 6: conv2 scatter (re-zero agg first)
    cudaMemsetAsync(p_agg, 0, (size_t)MAXN * W * sizeof(float), 0);
    scatter_kernel<<<sBlocks, sThreads>>>(src, dst, ew, (const float4*)h1, agg, E);

    // 7: conv2 GEMMs + bias + residual -> out
    gemm_kernel<1><<<gBlocks, 256>>>(agg, h1, Wrel2, brel2, Wroot2, x, out, n);
}

// round 2
// speedup vs baseline: 1.3556x; 1.3556x over previous
#include <cuda_runtime.h>
#include <cuda_bf16.h>

#define W 128
#define G 64
#define MAXN 100000
#define EPS 1e-5f

// ---------------- scratch (static device globals; no allocation) -------------
__device__ float g_xn[MAXN * W];
__device__ float g_agg[MAXN * W];
__device__ float g_h1[MAXN * W];
__device__ float g_sum[G * W];
__device__ float g_sumsq[G * W];
__device__ float g_alpha[G * W];
__device__ float g_beta[G * W];
__device__ float g_cnt[G];
__device__ float g_Wt[4 * W * W];   // transposed weights: [rel1, root1, rel2, root2]

// ---------------- packed f32x2 helpers ---------------------------------------
__device__ __forceinline__ unsigned long long pk2(float x) {
    unsigned long long r;
    asm("mov.b64 %0, {%1, %1};" : "=l"(r) : "f"(x));
    return r;
}
__device__ __forceinline__ void ffma2(unsigned long long& acc, unsigned long long a,
                                      unsigned long long b) {
    asm("fma.rn.f32x2 %0, %1, %2, %0;" : "+l"(acc) : "l"(a), "l"(b));
}
__device__ __forceinline__ void unpk(unsigned long long v, float& lo, float& hi) {
    asm("mov.b64 {%0, %1}, %2;" : "=f"(lo), "=f"(hi) : "l"(v));
}

// ---------------- 1. per-graph stats (batch_map is sorted) ------------------
__global__ __launch_bounds__(128) void stats_kernel(
    const float* __restrict__ x, const int* __restrict__ bmap, int n, int chunk)
{
    int n0 = blockIdx.x * chunk;
    if (n0 >= n) return;
    int n1 = min(n0 + chunk, n);
    int f = threadIdx.x;

    float s = 0.f, ss = 0.f;
    int curg = bmap[n0];
    int runStart = n0;
    for (int r = n0; r < n1; r++) {
        int g = bmap[r];
        if (g != curg) {
            atomicAdd(&g_sum[curg * W + f], s);
            atomicAdd(&g_sumsq[curg * W + f], ss);
            if (f == 0) atomicAdd(&g_cnt[curg], (float)(r - runStart));
            s = 0.f; ss = 0.f; curg = g; runStart = r;
        }
        float v = x[(size_t)r * W + f];
        s += v; ss += v * v;
    }
    atomicAdd(&g_sum[curg * W + f], s);
    atomicAdd(&g_sumsq[curg * W + f], ss);
    if (f == 0) atomicAdd(&g_cnt[curg], (float)(n1 - runStart));
}

// ---------------- 2. finalize per-(graph,feature) affine --------------------
__global__ __launch_bounds__(128) void finalize_kernel(
    const float* __restrict__ gnw, const float* __restrict__ gnb,
    const float* __restrict__ msc)
{
    int g = blockIdx.x, f = threadIdx.x;
    float cnt  = g_cnt[g];
    float inv  = (cnt > 0.f) ? (1.f / cnt) : 0.f;
    float mean = g_sum[g * W + f] * inv;
    float q    = g_sumsq[g * W + f] * inv;
    float m    = msc[f];
    float var  = q - mean * mean * m * (2.f - m);
    float istd = rsqrtf(var + EPS);
    float a    = gnw[f] * istd;
    g_alpha[g * W + f] = a;
    g_beta[g * W + f]  = gnb[f] - a * m * mean;
}

// ---------------- 2b. weight transpose (once per launch, tiny) ---------------
__global__ __launch_bounds__(256) void wtrans_kernel(
    const float* __restrict__ W0, const float* __restrict__ W1,
    const float* __restrict__ W2, const float* __restrict__ W3)
{
    __shared__ float t[32][33];
    const float* src = (blockIdx.z == 0) ? W0 : (blockIdx.z == 1) ? W1
                     : (blockIdx.z == 2) ? W2 : W3;
    float* dst = g_Wt + blockIdx.z * W * W;
    int bx = blockIdx.x * 32, by = blockIdx.y * 32;
    int tx = threadIdx.x & 31, ty = threadIdx.x >> 5;  // 32 x 8
    #pragma unroll
    for (int i = 0; i < 32; i += 8)
        t[ty + i][tx] = src[(by + ty + i) * W + bx + tx];
    __syncthreads();
    #pragma unroll
    for (int i = 0; i < 32; i += 8)
        dst[(bx + ty + i) * W + by + tx] = t[tx][ty + i];
}

// ---------------- 3. normalize + zero agg (float4 vectorized) ---------------
__global__ __launch_bounds__(256) void norm4_kernel(
    const float4* __restrict__ x, const int* __restrict__ bmap, int total)
{
    int idx = blockIdx.x * 256 + threadIdx.x;
    if (idx >= total) return;
    int r = idx >> 5, c = idx & 31;
    int g = __ldg(bmap + r);
    float4 xv = __ldg(x + idx);
    const float4* al = (const float4*)g_alpha + g * 32 + c;
    const float4* be = (const float4*)g_beta  + g * 32 + c;
    float4 a = *al, b = *be;
    float4 o;
    o.x = fmaf(a.x, xv.x, b.x);
    o.y = fmaf(a.y, xv.y, b.y);
    o.z = fmaf(a.z, xv.z, b.z);
    o.w = fmaf(a.w, xv.w, b.w);
    ((float4*)g_xn)[idx] = o;
    ((float4*)g_agg)[idx] = make_float4(0.f, 0.f, 0.f, 0.f);
}

// ---------------- 4. edge scatter: agg[dst] += ew * in[src] -----------------
__global__ __launch_bounds__(256) void scatter_kernel(
    const int* __restrict__ src, const int* __restrict__ dst,
    const float* __restrict__ ew, const float4* __restrict__ in,
    float* __restrict__ agg, int E)
{
    int idx = blockIdx.x * blockDim.x + threadIdx.x;
    int total = E * 32;
    if (idx >= total) return;
    int e = idx >> 5;
    int c = idx & 31;
    int s = __ldg(src + e);
    int d = __ldg(dst + e);
    float w = __ldg(ew + e);
    float4 v = __ldg(in + (size_t)s * 32 + c);
    float4 m; m.x = v.x * w; m.y = v.y * w; m.z = v.z * w; m.w = v.w * w;
    float* p = agg + (size_t)d * W + c * 4;
    asm volatile("red.global.add.v4.f32 [%0], {%1,%2,%3,%4};"
                 :: "l"(p), "f"(m.x), "f"(m.y), "f"(m.z), "f"(m.w) : "memory");
}

// ---------------- 5. fused dual-GEMM + epilogue (f32x2) ----------------------
// out[r,:] = epilogue( A[r,:] @ WtRel + B[r,:] @ WtRoot + brel )
// WtRel/WtRoot pre-transposed: Wt[k][c].
// CTA: 256 threads, tile 192 rows x 128 cols; thread = 12 rows x 8 cols
// (cols split as {tc*4 .. tc*4+3} and {64+tc*4 .. 64+tc*4+3} for conflict-free
//  contiguous weight LDS.128). Input tile XOR-swizzled on k-quad.
// MODE 0: LeakyReLU(0.1)   MODE 1: + residual
#define BM 192
#define BK 32

template <int MODE>
__global__ __launch_bounds__(256, 1) void gemm2_kernel(
    const float* __restrict__ A, const float* __restrict__ B,
    const float* __restrict__ WtRel, const float* __restrict__ WtRoot,
    const float* __restrict__ brel, const float* __restrict__ resid,
    float* __restrict__ out, int n)
{
    __shared__ float sIn[BM * 36];     // sIn[r][q-quad swizzled], stride 36 words
    __shared__ float sW[BK * 132];     // sW[k][c], stride 132 words

    int tid = threadIdx.x;
    int tr  = tid >> 4;                // 0..15 -> rows tr*12 .. tr*12+11
    int tc  = tid & 15;                // cols tc*4 and 64+tc*4
    int r0  = blockIdx.x * BM;

    unsigned long long acc[12][4];
    #pragma unroll
    for (int j = 0; j < 12; j++)
        #pragma unroll
        for (int m = 0; m < 4; m++) acc[j][m] = 0ULL;

    #pragma unroll 1
    for (int pass = 0; pass < 2; pass++) {
        const float* In = pass ? B : A;
        const float* Wt = pass ? WtRoot : WtRel;
        #pragma unroll 1
        for (int k0 = 0; k0 < W; k0 += BK) {
            __syncthreads();
            // stage input tile: 192 rows x 8 quads = 1536 float4, 6 iters
            #pragma unroll
            for (int i = 0; i < 6; i++) {
                int lin = tid + i * 256;
                int r = lin >> 3, q = lin & 7;
                int gr = r0 + r;
                float4 v = make_float4(0.f, 0.f, 0.f, 0.f);
                if (gr < n) v = __ldg((const float4*)In + (size_t)gr * 32 + (k0 >> 2) + q);
                *(float4*)&sIn[r * 36 + ((q ^ (r & 7)) << 2)] = v;
            }
            // stage weight tile: 32 k x 32 quads = 1024 float4, 4 iters
            #pragma unroll
            for (int i = 0; i < 4; i++) {
                int lin = tid + i * 256;
                int k = lin >> 5, cq = lin & 31;
                float4 v = __ldg((const float4*)Wt + (size_t)(k0 + k) * 32 + cq);
                *(float4*)&sW[k * 132 + cq * 4] = v;
            }
            __syncthreads();

            #pragma unroll
            for (int g = 0; g < 8; g++) {
                float4 a4[12];
                #pragma unroll
                for (int j = 0; j < 12; j++) {
                    int R = tr * 12 + j;
                    a4[j] = *(const float4*)&sIn[R * 36 + ((g ^ (R & 7)) << 2)];
                }
                #pragma unroll
                for (int kk = 0; kk < 4; kk++) {
                    const float* wp = &sW[(g * 4 + kk) * 132 + tc * 4];
                    ulonglong2 w0 = *(const ulonglong2*)wp;
                    ulonglong2 w1 = *(const ulonglong2*)(wp + 64);
                    #pragma unroll
                    for (int j = 0; j < 12; j++) {
                        float av = (kk == 0) ? a4[j].x : (kk == 1) ? a4[j].y
                                 : (kk == 2) ? a4[j].z : a4[j].w;
                        unsigned long long a2 = pk2(av);
                        ffma2(acc[j][0], a2, w0.x);
                        ffma2(acc[j][1], a2, w0.y);
                        ffma2(acc[j][2], a2, w1.x);
                        ffma2(acc[j][3], a2, w1.y);
                    }
                }
            }
        }
    }

    // epilogue
    float bv[8];
    #pragma unroll
    for (int m = 0; m < 4; m++) {
        bv[m]     = __ldg(brel + tc * 4 + m);
        bv[m + 4] = __ldg(brel + 64 + tc * 4 + m);
    }

    #pragma unroll
    for (int j = 0; j < 12; j++) {
        int r = r0 + tr * 12 + j;
        if (r >= n) continue;
        float v[8];
        unpk(acc[j][0], v[0], v[1]);
        unpk(acc[j][1], v[2], v[3]);
        unpk(acc[j][2], v[4], v[5]);
        unpk(acc[j][3], v[6], v[7]);
        #pragma unroll
        for (int m = 0; m < 8; m++) {
            v[m] += bv[m];
            if (MODE == 0) v[m] = (v[m] >= 0.f) ? v[m] : 0.1f * v[m];
        }
        if (MODE == 1) {
            float4 ra = __ldg((const float4*)(resid + (size_t)r * W + tc * 4));
            float4 rb = __ldg((const float4*)(resid + (size_t)r * W + 64 + tc * 4));
            v[0] += ra.x; v[1] += ra.y; v[2] += ra.z; v[3] += ra.w;
            v[4] += rb.x; v[5] += rb.y; v[6] += rb.z; v[7] += rb.w;
        }
        *(float4*)(out + (size_t)r * W + tc * 4)      = make_float4(v[0], v[1], v[2], v[3]);
        *(float4*)(out + (size_t)r * W + 64 + tc * 4) = make_float4(v[4], v[5], v[6], v[7]);
    }
}

// ---------------- launch -----------------------------------------------------
extern "C" void kernel_launch(void* const* d_in, const int* in_sizes, int n_in,
                              void* d_out, int out_size)
{
    const float* x      = (const float*)d_in[0];
    const int*   eidx   = (const int*)d_in[1];
    const float* ew     = (const float*)d_in[2];
    const int*   bmap   = (const int*)d_in[3];
    const float* gnw    = (const float*)d_in[4];
    const float* gnb    = (const float*)d_in[5];
    const float* msc    = (const float*)d_in[6];
    const float* Wrel1  = (const float*)d_in[7];
    const float* brel1  = (const float*)d_in[8];
    const float* Wroot1 = (const float*)d_in[9];
    const float* Wrel2  = (const float*)d_in[10];
    const float* brel2  = (const float*)d_in[11];
    const float* Wroot2 = (const float*)d_in[12];
    float* out = (float*)d_out;

    int n = in_sizes[0] / W;
    int E = in_sizes[2];
    const int* src = eidx;
    const int* dst = eidx + E;

    void *p_sum, *p_sumsq, *p_cnt, *p_xn, *p_agg, *p_h1, *p_wt;
    cudaGetSymbolAddress(&p_sum, g_sum);
    cudaGetSymbolAddress(&p_sumsq, g_sumsq);
    cudaGetSymbolAddress(&p_cnt, g_cnt);
    cudaGetSymbolAddress(&p_xn, g_xn);
    cudaGetSymbolAddress(&p_agg, g_agg);
    cudaGetSymbolAddress(&p_h1, g_h1);
    cudaGetSymbolAddress(&p_wt, g_Wt);
    float* agg = (float*)p_agg;
    float* xn  = (float*)p_xn;
    float* h1  = (float*)p_h1;
    float* Wt  = (float*)p_wt;

    cudaMemsetAsync(p_sum,   0, G * W * sizeof(float), 0);
    cudaMemsetAsync(p_sumsq, 0, G * W * sizeof(float), 0);
    cudaMemsetAsync(p_cnt,   0, G * sizeof(float), 0);

    // 1-2: GraphNorm stats + affine coefficients; weight transpose
    const int CHUNK = 256;
    int nblk = (n + CHUNK - 1) / CHUNK;
    stats_kernel<<<nblk, 128>>>(x, bmap, n, CHUNK);
    finalize_kernel<<<G, 128>>>(gnw, gnb, msc);
    wtrans_kernel<<<dim3(4, 4, 4), 256>>>(Wrel1, Wroot1, Wrel2, Wroot2);

    // 3: normalize + zero agg
    int total4 = n * 32;
    norm4_kernel<<<(total4 + 255) / 256, 256>>>((const float4*)x, bmap, total4);

    // 4: conv1 scatter
    int sThreads = 256;
    int sBlocks  = (E * 32 + sThreads - 1) / sThreads;
    scatter_kernel<<<sBlocks, sThreads>>>(src, dst, ew, (const float4*)xn, agg, E);

    // 5: conv1 GEMMs + bias + LeakyReLU -> h1
    int gBlocks = (n + BM - 1) / BM;
    gemm2_kernel<0><<<gBlocks, 256>>>(agg, xn, Wt, Wt + W * W, brel1, nullptr, h1, n);

    // 6: conv2 scatter (re-zero agg first)
    cudaMemsetAsync(p_agg, 0, (size_t)MAXN * W * sizeof(float), 0);
    scatter_kernel<<<sBlocks, sThreads>>>(src, dst, ew, (const float4*)h1, agg, E);

    // 7: conv2 GEMMs + bias + residual -> out
    gemm2_kernel<1><<<gBlocks, 256>>>(agg, h1, Wt + 2 * W * W, Wt + 3 * W * W,
                                      brel2, x, out, n);
}

// round 4
// speedup vs baseline: 2.0867x; 1.5393x over previous
#include <cuda_runtime.h>
#include <cuda_bf16.h>
#include <cstdint>

#define W 128
#define G 64
#define MAXN 100000
#define EPS 1e-5f

// ---------------- scratch (static device globals; no allocation) -------------
__device__ float g_xn[MAXN * W];
__device__ float g_agg[MAXN * W];
__device__ float g_h1[MAXN * W];
__device__ float g_sum[G * W];
__device__ float g_sumsq[G * W];
__device__ float g_alpha[G * W];
__device__ float g_beta[G * W];
__device__ float g_cnt[G];

// ---------------- PTX helpers (sm_80/90 baseline only — no 'a' features) -----
__device__ __forceinline__ uint32_t smem_u32(const void* p) {
    uint32_t a;
    asm("{ .reg .u64 t; cvta.to.shared.u64 t, %1; cvt.u32.u64 %0, t; }"
        : "=r"(a) : "l"(p));
    return a;
}
__device__ __forceinline__ uint32_t tf32r(float f) {
    uint32_t r;
    asm("cvt.rna.tf32.f32 %0, %1;" : "=r"(r) : "f"(f));
    return r;
}
__device__ __forceinline__ void ldsm4(uint4& r, uint32_t addr) {
    asm volatile("ldmatrix.sync.aligned.m8n8.x4.shared.b16 {%0,%1,%2,%3}, [%4];"
                 : "=r"(r.x), "=r"(r.y), "=r"(r.z), "=r"(r.w) : "r"(addr));
}
__device__ __forceinline__ void mma1688(float* d, const uint4& a,
                                        uint32_t b0, uint32_t b1) {
    asm volatile(
        "mma.sync.aligned.m16n8k8.row.col.f32.tf32.tf32.f32 "
        "{%0,%1,%2,%3}, {%4,%5,%6,%7}, {%8,%9}, {%0,%1,%2,%3};"
        : "+f"(d[0]), "+f"(d[1]), "+f"(d[2]), "+f"(d[3])
        : "r"(a.x), "r"(a.y), "r"(a.z), "r"(a.w), "r"(b0), "r"(b1));
}

// ---------------- 1. per-graph stats (batch_map is sorted) ------------------
__global__ __launch_bounds__(128) void stats_kernel(
    const float* __restrict__ x, const int* __restrict__ bmap, int n, int chunk)
{
    int n0 = blockIdx.x * chunk;
    if (n0 >= n) return;
    int n1 = min(n0 + chunk, n);
    int f = threadIdx.x;

    float s = 0.f, ss = 0.f;
    int curg = bmap[n0];
    int runStart = n0;
    for (int r = n0; r < n1; r++) {
        int g = bmap[r];
        if (g != curg) {
            atomicAdd(&g_sum[curg * W + f], s);
            atomicAdd(&g_sumsq[curg * W + f], ss);
            if (f == 0) atomicAdd(&g_cnt[curg], (float)(r - runStart));
            s = 0.f; ss = 0.f; curg = g; runStart = r;
        }
        float v = x[(size_t)r * W + f];
        s += v; ss += v * v;
    }
    atomicAdd(&g_sum[curg * W + f], s);
    atomicAdd(&g_sumsq[curg * W + f], ss);
    if (f == 0) atomicAdd(&g_cnt[curg], (float)(n1 - runStart));
}

// ---------------- 2. finalize per-(graph,feature) affine --------------------
__global__ __launch_bounds__(128) void finalize_kernel(
    const float* __restrict__ gnw, const float* __restrict__ gnb,
    const float* __restrict__ msc)
{
    int g = blockIdx.x, f = threadIdx.x;
    float cnt  = g_cnt[g];
    float inv  = (cnt > 0.f) ? (1.f / cnt) : 0.f;
    float mean = g_sum[g * W + f] * inv;
    float q    = g_sumsq[g * W + f] * inv;
    float m    = msc[f];
    float var  = q - mean * mean * m * (2.f - m);
    float istd = rsqrtf(var + EPS);
    float a    = gnw[f] * istd;
    g_alpha[g * W + f] = a;
    g_beta[g * W + f]  = gnb[f] - a * m * mean;
}

// ---------------- 3. normalize + zero agg (float4 vectorized) ---------------
__global__ __launch_bounds__(256) void norm4_kernel(
    const float4* __restrict__ x, const int* __restrict__ bmap, int total)
{
    int idx = blockIdx.x * 256 + threadIdx.x;
    if (idx >= total) return;
    int r = idx >> 5, c = idx & 31;
    int g = __ldg(bmap + r);
    float4 xv = __ldg(x + idx);
    float4 a = ((const float4*)g_alpha)[g * 32 + c];
    float4 b = ((const float4*)g_beta)[g * 32 + c];
    float4 o;
    o.x = fmaf(a.x, xv.x, b.x);
    o.y = fmaf(a.y, xv.y, b.y);
    o.z = fmaf(a.z, xv.z, b.z);
    o.w = fmaf(a.w, xv.w, b.w);
    ((float4*)g_xn)[idx] = o;
    ((float4*)g_agg)[idx] = make_float4(0.f, 0.f, 0.f, 0.f);
}

// ---------------- 4. edge scatter: agg[dst] += ew * in[src] -----------------
__global__ __launch_bounds__(256) void scatter_kernel(
    const int* __restrict__ src, const int* __restrict__ dst,
    const float* __restrict__ ew, const float4* __restrict__ in,
    float* __restrict__ agg, int E)
{
    int idx = blockIdx.x * blockDim.x + threadIdx.x;
    int total = E * 32;
    if (idx >= total) return;
    int e = idx >> 5;
    int c = idx & 31;
    int s = __ldg(src + e);
    int d = __ldg(dst + e);
    float w = __ldg(ew + e);
    float4 v = __ldg(in + (size_t)s * 32 + c);
    float4 m; m.x = v.x * w; m.y = v.y * w; m.z = v.z * w; m.w = v.w * w;
    float* p = agg + (size_t)d * W + c * 4;
    asm volatile("red.global.add.v4.f32 [%0], {%1,%2,%3,%4};"
                 :: "l"(p), "f"(m.x), "f"(m.y), "f"(m.z), "f"(m.w) : "memory");
}

// ---------------- 5. warp-MMA tf32 GEMM: out = epi([A|B]@[Wrel;Wroot]^T) ----
// CTA: 256 threads / 8 warps; tile 128 rows x 128 cols; combined K=256 in 8
// chunks of 32 (chunks 0-3: agg vs Wrel, 4-7: in vs Wroot). Double-buffered.
// Warp = 32 rows x 64 cols = 2 x 8 tiles of mma.m16n8k8.tf32.
// MODE 0: LeakyReLU(0.1)   MODE 1: + residual
#define TC_A0      1024
#define TC_B0      17408
#define TC_A1      33792
#define TC_B1      50176
#define TC_SMEM_TOTAL 66560

__device__ __forceinline__ void stage_chunk(
    char* smem, int b, int tid, int r0, int n, int c,
    const float* __restrict__ Arel, const float* __restrict__ Aroot,
    const float* __restrict__ Wrel, const float* __restrict__ Wroot)
{
    const float* As; const float* Bs; int kloc;
    if (c < 4) { As = Arel;  Bs = Wrel;  kloc = c * 32; }
    else       { As = Aroot; Bs = Wroot; kloc = (c - 4) * 32; }
    char* sa = smem + (b ? TC_A1 : TC_A0);
    char* sb = smem + (b ? TC_B1 : TC_B0);
    // A: 128 rows x 8 quads (32 k)
    #pragma unroll
    for (int i = 0; i < 4; i++) {
        int q = tid + i * 256;
        int row = q >> 3, cq = q & 7;
        int gr = r0 + row;
        float4 v = make_float4(0.f, 0.f, 0.f, 0.f);
        if (gr < n) v = __ldg((const float4*)(As + (size_t)gr * W + kloc) + cq);
        uint4 t; t.x = tf32r(v.x); t.y = tf32r(v.y); t.z = tf32r(v.z); t.w = tf32r(v.w);
        *(uint4*)(sa + row * 128 + ((cq ^ (row & 7)) << 4)) = t;
    }
    // B (weights, stored [n][k]): 128 n-rows x 8 quads
    #pragma unroll
    for (int i = 0; i < 4; i++) {
        int q = tid + i * 256;
        int row = q >> 3, cq = q & 7;
        float4 v = __ldg((const float4*)(Bs + (size_t)row * W + kloc) + cq);
        uint4 t; t.x = tf32r(v.x); t.y = tf32r(v.y); t.z = tf32r(v.z); t.w = tf32r(v.w);
        *(uint4*)(sb + row * 128 + ((cq ^ (row & 7)) << 4)) = t;
    }
}

template <int MODE>
__global__ __launch_bounds__(256) void gemm_mma_kernel(
    const float* __restrict__ Arel, const float* __restrict__ Aroot,
    const float* __restrict__ Wrel, const float* __restrict__ Wroot,
    const float* __restrict__ brel, const float* __restrict__ resid,
    float* __restrict__ out, int n)
{
    extern __shared__ char smem[];
    uint32_t sbase = smem_u32(smem);
    int tid = threadIdx.x, wid = tid >> 5, lane = tid & 31;
    int wm = wid & 3, wn = wid >> 2;
    int r0 = blockIdx.x * 128;

    if (tid < 128) ((float*)smem)[tid] = __ldg(brel + tid);  // bias at offset 0

    float acc[2][8][4];
    #pragma unroll
    for (int t = 0; t < 2; t++)
        #pragma unroll
        for (int u = 0; u < 8; u++)
            #pragma unroll
            for (int v = 0; v < 4; v++) acc[t][u][v] = 0.f;

    // ldmatrix address components
    int j = lane & 7, grp = lane >> 3;
    int arow0 = wm * 32 + ((grp & 1) << 3) + j;   // + t*16
    int abit  = grp >> 1;                         // k-quad low bit for A
    int brow0 = wn * 64 + ((grp >> 1) << 3) + j;  // + p*16
    int bbit  = grp & 1;                          // k-quad low bit for B

    stage_chunk(smem, 0, tid, r0, n, 0, Arel, Aroot, Wrel, Wroot);

    #pragma unroll 1
    for (int c = 0; c < 8; c++) {
        __syncthreads();
        if (c < 7)
            stage_chunk(smem, (c + 1) & 1, tid, r0, n, c + 1, Arel, Aroot, Wrel, Wroot);
        uint32_t aB = sbase + ((c & 1) ? TC_A1 : TC_A0);
        uint32_t bB = sbase + ((c & 1) ? TC_B1 : TC_B0);
        #pragma unroll
        for (int s = 0; s < 4; s++) {
            uint4 af[2];
            #pragma unroll
            for (int t = 0; t < 2; t++) {
                int row = arow0 + t * 16;
                ldsm4(af[t], aB + row * 128 + (((s * 2 + abit) ^ (row & 7)) << 4));
            }
            uint4 bf[4];
            #pragma unroll
            for (int p = 0; p < 4; p++) {
                int row = brow0 + p * 16;
                ldsm4(bf[p], bB + row * 128 + (((s * 2 + bbit) ^ (row & 7)) << 4));
            }
            #pragma unroll
            for (int t = 0; t < 2; t++)
                #pragma unroll
                for (int u = 0; u < 8; u++) {
                    int p = u >> 1;
                    uint32_t b0 = (u & 1) ? bf[p].z : bf[p].x;
                    uint32_t b1 = (u & 1) ? bf[p].w : bf[p].y;
                    mma1688(acc[t][u], af[t], b0, b1);
                }
        }
    }

    // epilogue: c-fragment (rows lane/4, +8; cols 2*(lane%4)+{0,1})
    const float* bias = (const float*)smem;
    int rb = r0 + wm * 32 + (lane >> 2);
    int cb = wn * 64 + ((lane & 3) << 1);
    #pragma unroll
    for (int t = 0; t < 2; t++) {
        #pragma unroll
        for (int u = 0; u < 8; u++) {
            int cc = cb + u * 8;
            float b0v = bias[cc], b1v = bias[cc + 1];
            #pragma unroll
            for (int h = 0; h < 2; h++) {
                int r = rb + t * 16 + h * 8;
                if (r >= n) continue;
                float vx = acc[t][u][h * 2 + 0] + b0v;
                float vy = acc[t][u][h * 2 + 1] + b1v;
                if (MODE == 0) {
                    vx = (vx >= 0.f) ? vx : 0.1f * vx;
                    vy = (vy >= 0.f) ? vy : 0.1f * vy;
                } else {
                    float2 rr = *(const float2*)(resid + (size_t)r * W + cc);
                    vx += rr.x; vy += rr.y;
                }
                *(float2*)(out + (size_t)r * W + cc) = make_float2(vx, vy);
            }
        }
    }
}

// ---------------- launch -----------------------------------------------------
extern "C" void kernel_launch(void* const* d_in, const int* in_sizes, int n_in,
                              void* d_out, int out_size)
{
    const float* x      = (const float*)d_in[0];
    const int*   eidx   = (const int*)d_in[1];
    const float* ew     = (const float*)d_in[2];
    const int*   bmap   = (const int*)d_in[3];
    const float* gnw    = (const float*)d_in[4];
    const float* gnb    = (const float*)d_in[5];
    const float* msc    = (const float*)d_in[6];
    const float* Wrel1  = (const float*)d_in[7];
    const float* brel1  = (const float*)d_in[8];
    const float* Wroot1 = (const float*)d_in[9];
    const float* Wrel2  = (const float*)d_in[10];
    const float* brel2  = (const float*)d_in[11];
    const float* Wroot2 = (const float*)d_in[12];
    float* out = (float*)d_out;

    int n = in_sizes[0] / W;
    int E = in_sizes[2];
    const int* src = eidx;
    const int* dst = eidx + E;

    void *p_sum, *p_sumsq, *p_cnt, *p_xn, *p_agg, *p_h1;
    cudaGetSymbolAddress(&p_sum, g_sum);
    cudaGetSymbolAddress(&p_sumsq, g_sumsq);
    cudaGetSymbolAddress(&p_cnt, g_cnt);
    cudaGetSymbolAddress(&p_xn, g_xn);
    cudaGetSymbolAddress(&p_agg, g_agg);
    cudaGetSymbolAddress(&p_h1, g_h1);
    float* agg = (float*)p_agg;
    float* xn  = (float*)p_xn;
    float* h1  = (float*)p_h1;

    cudaFuncSetAttribute(gemm_mma_kernel<0>,
                         cudaFuncAttributeMaxDynamicSharedMemorySize, TC_SMEM_TOTAL);
    cudaFuncSetAttribute(gemm_mma_kernel<1>,
                         cudaFuncAttributeMaxDynamicSharedMemorySize, TC_SMEM_TOTAL);

    cudaMemsetAsync(p_sum,   0, G * W * sizeof(float), 0);
    cudaMemsetAsync(p_sumsq, 0, G * W * sizeof(float), 0);
    cudaMemsetAsync(p_cnt,   0, G * sizeof(float), 0);

    // 1-2: GraphNorm stats + affine coefficients
    const int CHUNK = 256;
    int nblk = (n + CHUNK - 1) / CHUNK;
    stats_kernel<<<nblk, 128>>>(x, bmap, n, CHUNK);
    finalize_kernel<<<G, 128>>>(gnw, gnb, msc);

    // 3: normalize + zero agg
    int total4 = n * 32;
    norm4_kernel<<<(total4 + 255) / 256, 256>>>((const float4*)x, bmap, total4);

    // 4: conv1 scatter
    int sThreads = 256;
    int sBlocks  = (E * 32 + sThreads - 1) / sThreads;
    scatter_kernel<<<sBlocks, sThreads>>>(src, dst, ew, (const float4*)xn, agg, E);

    // 5: conv1 GEMM (tensor cores) + bias + LeakyReLU -> h1
    int gBlocks = (n + 127) / 128;
    gemm_mma_kernel<0><<<gBlocks, 256, TC_SMEM_TOTAL>>>(
        agg, xn, Wrel1, Wroot1, brel1, nullptr, h1, n);

    // 6: conv2 scatter (re-zero agg first)
    cudaMemsetAsync(p_agg, 0, (size_t)MAXN * W * sizeof(float), 0);
    scatter_kernel<<<sBlocks, sThreads>>>(src, dst, ew, (const float4*)h1, agg, E);

    // 7: conv2 GEMM (tensor cores) + bias + residual -> out
    gemm_mma_kernel<1><<<gBlocks, 256, TC_SMEM_TOTAL>>>(
        agg, h1, Wrel2, Wroot2, brel2, x, out, n);
}

// round 5
// speedup vs baseline: 2.4339x; 1.1664x over previous
#include <cuda_runtime.h>
#include <cuda_bf16.h>
#include <cstdint>

#define W 128
#define G 64
#define MAXN 100000
#define MAXE 625000
#define EPS 1e-5f

// ---------------- scratch (static device globals; no allocation) -------------
__device__ float g_xn[MAXN * W];
__device__ float g_agg[MAXN * W];
__device__ float g_h1[MAXN * W];
__device__ float g_sum[G * W];
__device__ float g_sumsq[G * W];
__device__ float g_alpha[G * W];
__device__ float g_beta[G * W];
__device__ float g_cnt[G];
__device__ int   g_deg[MAXN];
__device__ int   g_base[MAXN + 4];
__device__ int   g_cur[MAXN];
__device__ int2  g_elist[MAXE];
__device__ int   g_bsum[64];

// ---------------- PTX helpers (sm_80/90 baseline only) -----------------------
__device__ __forceinline__ uint32_t smem_u32(const void* p) {
    uint32_t a;
    asm("{ .reg .u64 t; cvta.to.shared.u64 t, %1; cvt.u32.u64 %0, t; }"
        : "=r"(a) : "l"(p));
    return a;
}
__device__ __forceinline__ uint32_t tf32r(float f) {
    uint32_t r;
    asm("cvt.rna.tf32.f32 %0, %1;" : "=r"(r) : "f"(f));
    return r;
}
__device__ __forceinline__ void ldsm4(uint4& r, uint32_t addr) {
    asm volatile("ldmatrix.sync.aligned.m8n8.x4.shared.b16 {%0,%1,%2,%3}, [%4];"
                 : "=r"(r.x), "=r"(r.y), "=r"(r.z), "=r"(r.w) : "r"(addr));
}
__device__ __forceinline__ void mma1688(float* d, const uint4& a,
                                        uint32_t b0, uint32_t b1) {
    asm volatile(
        "mma.sync.aligned.m16n8k8.row.col.f32.tf32.tf32.f32 "
        "{%0,%1,%2,%3}, {%4,%5,%6,%7}, {%8,%9}, {%0,%1,%2,%3};"
        : "+f"(d[0]), "+f"(d[1]), "+f"(d[2]), "+f"(d[3])
        : "r"(a.x), "r"(a.y), "r"(a.z), "r"(a.w), "r"(b0), "r"(b1));
}

// ---------------- 1. per-graph stats (batch_map is sorted) ------------------
__global__ __launch_bounds__(128) void stats_kernel(
    const float* __restrict__ x, const int* __restrict__ bmap, int n, int chunk)
{
    int n0 = blockIdx.x * chunk;
    if (n0 >= n) return;
    int n1 = min(n0 + chunk, n);
    int f = threadIdx.x;

    float s = 0.f, ss = 0.f;
    int curg = bmap[n0];
    int runStart = n0;
    for (int r = n0; r < n1; r++) {
        int g = bmap[r];
        if (g != curg) {
            atomicAdd(&g_sum[curg * W + f], s);
            atomicAdd(&g_sumsq[curg * W + f], ss);
            if (f == 0) atomicAdd(&g_cnt[curg], (float)(r - runStart));
            s = 0.f; ss = 0.f; curg = g; runStart = r;
        }
        float v = x[(size_t)r * W + f];
        s += v; ss += v * v;
    }
    atomicAdd(&g_sum[curg * W + f], s);
    atomicAdd(&g_sumsq[curg * W + f], ss);
    if (f == 0) atomicAdd(&g_cnt[curg], (float)(n1 - runStart));
}

// ---------------- 2. finalize per-(graph,feature) affine --------------------
__global__ __launch_bounds__(128) void finalize_kernel(
    const float* __restrict__ gnw, const float* __restrict__ gnb,
    const float* __restrict__ msc)
{
    int g = blockIdx.x, f = threadIdx.x;
    float cnt  = g_cnt[g];
    float inv  = (cnt > 0.f) ? (1.f / cnt) : 0.f;
    float mean = g_sum[g * W + f] * inv;
    float q    = g_sumsq[g * W + f] * inv;
    float m    = msc[f];
    float var  = q - mean * mean * m * (2.f - m);
    float istd = rsqrtf(var + EPS);
    float a    = gnw[f] * istd;
    g_alpha[g * W + f] = a;
    g_beta[g * W + f]  = gnb[f] - a * m * mean;
}

// ---------------- 3. normalize (float4 vectorized) ---------------------------
__global__ __launch_bounds__(256) void norm4_kernel(
    const float4* __restrict__ x, const int* __restrict__ bmap, int total)
{
    int idx = blockIdx.x * 256 + threadIdx.x;
    if (idx >= total) return;
    int r = idx >> 5, c = idx & 31;
    int g = __ldg(bmap + r);
    float4 xv = __ldg(x + idx);
    float4 a = ((const float4*)g_alpha)[g * 32 + c];
    float4 b = ((const float4*)g_beta)[g * 32 + c];
    float4 o;
    o.x = fmaf(a.x, xv.x, b.x);
    o.y = fmaf(a.y, xv.y, b.y);
    o.z = fmaf(a.z, xv.z, b.z);
    o.w = fmaf(a.w, xv.w, b.w);
    ((float4*)g_xn)[idx] = o;
}

// ---------------- CSR build: hist -> scan1/2/3 -> place ----------------------
__global__ __launch_bounds__(256) void hist_kernel(const int* __restrict__ dst, int E)
{
    int e = blockIdx.x * 256 + threadIdx.x;
    if (e < E) atomicAdd(&g_deg[dst[e]], 1);
}

// scan1: per-block (4096 elems) sum -> g_bsum[b]
__global__ __launch_bounds__(256) void scan1_kernel(int n4)
{
    __shared__ int wS[8];
    int b = blockIdx.x, tid = threadIdx.x, lane = tid & 31, wid = tid >> 5;
    const int4* dp = (const int4*)g_deg;
    int i4 = b * 1024 + tid * 4;
    int s = 0;
    #pragma unroll
    for (int j = 0; j < 4; j++) {
        if (i4 + j < n4) {
            int4 v = dp[i4 + j];
            s += v.x + v.y + v.z + v.w;
        }
    }
    #pragma unroll
    for (int o = 16; o > 0; o >>= 1) s += __shfl_down_sync(~0u, s, o);
    if (lane == 0) wS[wid] = s;
    __syncthreads();
    if (tid == 0) {
        int t = 0;
        #pragma unroll
        for (int k = 0; k < 8; k++) t += wS[k];
        g_bsum[b] = t;
    }
}

// scan2: exclusive scan of block sums; writes g_base[n] = total
__global__ void scan2_kernel(int nb, int n)
{
    if (threadIdx.x == 0) {
        int run = 0;
        for (int i = 0; i < nb; i++) {
            int t = g_bsum[i];
            g_bsum[i] = run;
            run += t;
        }
        g_base[n] = run;
    }
}

// scan3: per-block exclusive scan + block offset -> g_base[0..n)
__global__ __launch_bounds__(256) void scan3_kernel(int n4)
{
    __shared__ int wS[8];
    int b = blockIdx.x, tid = threadIdx.x, lane = tid & 31, wid = tid >> 5;
    const int4* dp = (const int4*)g_deg;
    int i4 = b * 1024 + tid * 4;
    int4 v[4];
    int s = 0;
    #pragma unroll
    for (int j = 0; j < 4; j++) {
        v[j] = make_int4(0, 0, 0, 0);
        if (i4 + j < n4) v[j] = dp[i4 + j];
        s += v[j].x + v[j].y + v[j].z + v[j].w;
    }
    int x = s;
    #pragma unroll
    for (int o = 1; o < 32; o <<= 1) {
        int y = __shfl_up_sync(~0u, x, o);
        if (lane >= o) x += y;
    }
    if (lane == 31) wS[wid] = x;
    __syncthreads();
    int woff = 0;
    #pragma unroll
    for (int k = 0; k < 8; k++)
        if (k < wid) woff += wS[k];
    int run = g_bsum[b] + woff + x - s;
    int4* bp = (int4*)g_base;
    #pragma unroll
    for (int j = 0; j < 4; j++) {
        if (i4 + j < n4) {
            int4 o;
            o.x = run; run += v[j].x;
            o.y = run; run += v[j].y;
            o.z = run; run += v[j].z;
            o.w = run; run += v[j].w;
            bp[i4 + j] = o;
        }
    }
}

__global__ __launch_bounds__(256) void place_kernel(
    const int* __restrict__ src, const int* __restrict__ dst,
    const float* __restrict__ ew, int E)
{
    int e = blockIdx.x * 256 + threadIdx.x;
    if (e >= E) return;
    int d = dst[e];
    int p = g_base[d] + atomicAdd(&g_cur[d], 1);
    g_elist[p] = make_int2(src[e], __float_as_int(ew[e]));
}

// ---------------- gather: agg[r] = sum_{e in CSR(r)} w_e * in[src_e] ---------
__global__ __launch_bounds__(256) void gather_kernel(
    const float4* __restrict__ in, float4* __restrict__ agg, int n)
{
    int warp = (blockIdx.x * 256 + threadIdx.x) >> 5;
    if (warp >= n) return;
    int c = threadIdx.x & 31;
    int b0 = g_base[warp], b1 = g_base[warp + 1];
    float4 acc = make_float4(0.f, 0.f, 0.f, 0.f);
    int e = b0;
    #pragma unroll 1
    for (; e + 2 <= b1; e += 2) {
        int2 s0 = __ldg(&g_elist[e]);
        int2 s1 = __ldg(&g_elist[e + 1]);
        float4 v0 = __ldg(in + (size_t)s0.x * 32 + c);
        float4 v1 = __ldg(in + (size_t)s1.x * 32 + c);
        float w0 = __int_as_float(s0.y), w1 = __int_as_float(s1.y);
        acc.x = fmaf(w0, v0.x, acc.x); acc.y = fmaf(w0, v0.y, acc.y);
        acc.z = fmaf(w0, v0.z, acc.z); acc.w = fmaf(w0, v0.w, acc.w);
        acc.x = fmaf(w1, v1.x, acc.x); acc.y = fmaf(w1, v1.y, acc.y);
        acc.z = fmaf(w1, v1.z, acc.z); acc.w = fmaf(w1, v1.w, acc.w);
    }
    if (e < b1) {
        int2 s0 = __ldg(&g_elist[e]);
        float4 v0 = __ldg(in + (size_t)s0.x * 32 + c);
        float w0 = __int_as_float(s0.y);
        acc.x = fmaf(w0, v0.x, acc.x); acc.y = fmaf(w0, v0.y, acc.y);
        acc.z = fmaf(w0, v0.z, acc.z); acc.w = fmaf(w0, v0.w, acc.w);
    }
    agg[(size_t)warp * 32 + c] = acc;
}

// ---------------- warp-MMA tf32 GEMM: out = epi([A|B]@[Wrel;Wroot]^T) -------
// Weights: all 8 tf32 chunks preloaded to smem once (128KB, reused).
// A: double-buffered; LDG-to-regs issued before compute, cvt+STS after.
// MODE 0: LeakyReLU(0.1)   MODE 1: + residual
#define GM_A0    1024
#define GM_A1    (GM_A0 + 16384)
#define GM_WS    (GM_A1 + 16384)
#define GM_SMEM  (GM_WS + 8 * 16384)

__device__ __forceinline__ void ldgA(float4* regs, int tid, int r0, int n, int c,
                                     const float* __restrict__ Arel,
                                     const float* __restrict__ Aroot)
{
    const float* As = (c < 4) ? Arel : Aroot;
    int kloc = (c & 3) * 32;
    #pragma unroll
    for (int i = 0; i < 4; i++) {
        int q = tid + i * 256;
        int row = q >> 3, cq = q & 7;
        int gr = r0 + row;
        regs[i] = make_float4(0.f, 0.f, 0.f, 0.f);
        if (gr < n) regs[i] = __ldg((const float4*)(As + (size_t)gr * W + kloc) + cq);
    }
}
__device__ __forceinline__ void stsA(const float4* regs, char* sa, int tid)
{
    #pragma unroll
    for (int i = 0; i < 4; i++) {
        int q = tid + i * 256;
        int row = q >> 3, cq = q & 7;
        uint4 t;
        t.x = tf32r(regs[i].x); t.y = tf32r(regs[i].y);
        t.z = tf32r(regs[i].z); t.w = tf32r(regs[i].w);
        *(uint4*)(sa + row * 128 + ((cq ^ (row & 7)) << 4)) = t;
    }
}

template <int MODE>
__global__ __launch_bounds__(256) void gemm_mma_kernel(
    const float* __restrict__ Arel, const float* __restrict__ Aroot,
    const float* __restrict__ Wrel, const float* __restrict__ Wroot,
    const float* __restrict__ brel, const float* __restrict__ resid,
    float* __restrict__ out, int n)
{
    extern __shared__ char smem[];
    uint32_t sbase = smem_u32(smem);
    int tid = threadIdx.x, wid = tid >> 5, lane = tid & 31;
    int wm = wid & 3, wn = wid >> 2;
    int r0 = blockIdx.x * 128;

    if (tid < 128) ((float*)smem)[tid] = __ldg(brel + tid);  // bias at offset 0

    // preload all 8 weight chunks (tf32, swizzled)
    #pragma unroll 1
    for (int c = 0; c < 8; c++) {
        const float* Bs = (c < 4) ? Wrel : Wroot;
        int kloc = (c & 3) * 32;
        char* sb = smem + GM_WS + c * 16384;
        #pragma unroll
        for (int i = 0; i < 4; i++) {
            int q = tid + i * 256;
            int row = q >> 3, cq = q & 7;
            float4 v = __ldg((const float4*)(Bs + (size_t)row * W + kloc) + cq);
            uint4 t;
            t.x = tf32r(v.x); t.y = tf32r(v.y); t.z = tf32r(v.z); t.w = tf32r(v.w);
            *(uint4*)(sb + row * 128 + ((cq ^ (row & 7)) << 4)) = t;
        }
    }

    float acc[2][8][4];
    #pragma unroll
    for (int t = 0; t < 2; t++)
        #pragma unroll
        for (int u = 0; u < 8; u++)
            #pragma unroll
            for (int v = 0; v < 4; v++) acc[t][u][v] = 0.f;

    int j = lane & 7, grp = lane >> 3;
    int arow0 = wm * 32 + ((grp & 1) << 3) + j;
    int abit  = grp >> 1;
    int brow0 = wn * 64 + ((grp >> 1) << 3) + j;
    int bbit  = grp & 1;

    float4 ar[4];
    ldgA(ar, tid, r0, n, 0, Arel, Aroot);
    stsA(ar, smem + GM_A0, tid);

    #pragma unroll 1
    for (int c = 0; c < 8; c++) {
        if (c < 7) ldgA(ar, tid, r0, n, c + 1, Arel, Aroot);
        __syncthreads();
        uint32_t aB = sbase + ((c & 1) ? GM_A1 : GM_A0);
        uint32_t bB = sbase + GM_WS + (uint32_t)c * 16384;
        #pragma unroll
        for (int s = 0; s < 4; s++) {
            uint4 af[2];
            #pragma unroll
            for (int t = 0; t < 2; t++) {
                int row = arow0 + t * 16;
                ldsm4(af[t], aB + row * 128 + (((s * 2 + abit) ^ (row & 7)) << 4));
            }
            uint4 bf[4];
            #pragma unroll
            for (int p = 0; p < 4; p++) {
                int row = brow0 + p * 16;
                ldsm4(bf[p], bB + row * 128 + (((s * 2 + bbit) ^ (row & 7)) << 4));
            }
            #pragma unroll
            for (int t = 0; t < 2; t++)
                #pragma unroll
                for (int u = 0; u < 8; u++) {
                    int p = u >> 1;
                    uint32_t b0 = (u & 1) ? bf[p].z : bf[p].x;
                    uint32_t b1 = (u & 1) ? bf[p].w : bf[p].y;
                    mma1688(acc[t][u], af[t], b0, b1);
                }
        }
        if (c < 7)
            stsA(ar, smem + (((c + 1) & 1) ? GM_A1 : GM_A0), tid);
    }

    // epilogue
    const float* bias = (const float*)smem;
    int rb = r0 + wm * 32 + (lane >> 2);
    int cb = wn * 64 + ((lane & 3) << 1);
    #pragma unroll
    for (int t = 0; t < 2; t++) {
        #pragma unroll
        for (int u = 0; u < 8; u++) {
            int cc = cb + u * 8;
            float b0v = bias[cc], b1v = bias[cc + 1];
            #pragma unroll
            for (int h = 0; h < 2; h++) {
                int r = rb + t * 16 + h * 8;
                if (r >= n) continue;
                float vx = acc[t][u][h * 2 + 0] + b0v;
                float vy = acc[t][u][h * 2 + 1] + b1v;
                if (MODE == 0) {
                    vx = (vx >= 0.f) ? vx : 0.1f * vx;
                    vy = (vy >= 0.f) ? vy : 0.1f * vy;
                } else {
                    float2 rr = *(const float2*)(resid + (size_t)r * W + cc);
                    vx += rr.x; vy += rr.y;
                }
                *(float2*)(out + (size_t)r * W + cc) = make_float2(vx, vy);
            }
        }
    }
}

// ---------------- launch -----------------------------------------------------
extern "C" void kernel_launch(void* const* d_in, const int* in_sizes, int n_in,
                              void* d_out, int out_size)
{
    const float* x      = (const float*)d_in[0];
    const int*   eidx   = (const int*)d_in[1];
    const float* ew     = (const float*)d_in[2];
    const int*   bmap   = (const int*)d_in[3];
    const float* gnw    = (const float*)d_in[4];
    const float* gnb    = (const float*)d_in[5];
    const float* msc    = (const float*)d_in[6];
    const float* Wrel1  = (const float*)d_in[7];
    const float* brel1  = (const float*)d_in[8];
    const float* Wroot1 = (const float*)d_in[9];
    const float* Wrel2  = (const float*)d_in[10];
    const float* brel2  = (const float*)d_in[11];
    const float* Wroot2 = (const float*)d_in[12];
    float* out = (float*)d_out;

    int n = in_sizes[0] / W;
    int E = in_sizes[2];
    const int* src = eidx;
    const int* dst = eidx + E;

    void *p_sum, *p_sumsq, *p_cnt, *p_xn, *p_agg, *p_h1, *p_deg, *p_cur;
    cudaGetSymbolAddress(&p_sum, g_sum);
    cudaGetSymbolAddress(&p_sumsq, g_sumsq);
    cudaGetSymbolAddress(&p_cnt, g_cnt);
    cudaGetSymbolAddress(&p_xn, g_xn);
    cudaGetSymbolAddress(&p_agg, g_agg);
    cudaGetSymbolAddress(&p_h1, g_h1);
    cudaGetSymbolAddress(&p_deg, g_deg);
    cudaGetSymbolAddress(&p_cur, g_cur);
    float* agg = (float*)p_agg;
    float* xn  = (float*)p_xn;
    float* h1  = (float*)p_h1;

    cudaFuncSetAttribute(gemm_mma_kernel<0>,
                         cudaFuncAttributeMaxDynamicSharedMemorySize, GM_SMEM);
    cudaFuncSetAttribute(gemm_mma_kernel<1>,
                         cudaFuncAttributeMaxDynamicSharedMemorySize, GM_SMEM);

    cudaMemsetAsync(p_sum,   0, G * W * sizeof(float), 0);
    cudaMemsetAsync(p_sumsq, 0, G * W * sizeof(float), 0);
    cudaMemsetAsync(p_cnt,   0, G * sizeof(float), 0);
    cudaMemsetAsync(p_deg,   0, (size_t)n * sizeof(int), 0);
    cudaMemsetAsync(p_cur,   0, (size_t)n * sizeof(int), 0);

    // GraphNorm stats + affine
    const int CHUNK = 256;
    stats_kernel<<<(n + CHUNK - 1) / CHUNK, 128>>>(x, bmap, n, CHUNK);
    finalize_kernel<<<G, 128>>>(gnw, gnb, msc);

    // CSR build (shared by both convs)
    int n4 = (n + 3) / 4;
    int nscan = (n4 + 1023) / 1024;
    hist_kernel<<<(E + 255) / 256, 256>>>(dst, E);
    scan1_kernel<<<nscan, 256>>>(n4);
    scan2_kernel<<<1, 32>>>(nscan, n);
    scan3_kernel<<<nscan, 256>>>(n4);
    place_kernel<<<(E + 255) / 256, 256>>>(src, dst, ew, E);

    // normalize
    int total4 = n * 32;
    norm4_kernel<<<(total4 + 255) / 256, 256>>>((const float4*)x, bmap, total4);

    // conv1: gather + GEMM(+LeakyReLU)
    int gwBlocks = (n * 32 + 255) / 256;
    gather_kernel<<<gwBlocks, 256>>>((const float4*)xn, (float4*)agg, n);
    int gBlocks = (n + 127) / 128;
    gemm_mma_kernel<0><<<gBlocks, 256, GM_SMEM>>>(
        agg, xn, Wrel1, Wroot1, brel1, nullptr, h1, n);

    // conv2: gather + GEMM(+residual)
    gather_kernel<<<gwBlocks, 256>>>((const float4*)h1, (float4*)agg, n);
    gemm_mma_kernel<1><<<gBlocks, 256, GM_SMEM>>>(
        agg, h1, Wrel2, Wroot2, brel2, x, out, n);
}

// round 6
// speedup vs baseline: 3.4226x; 1.4062x over previous
#include <cuda_runtime.h>
#include <cuda_fp16.h>
#include <cstdint>

#define W 128
#define G 64
#define MAXN 100000
#define MAXE 625000
#define EPS 1e-5f

// ---------------- scratch (static device globals; no allocation) -------------
__device__ __half g_xnh[MAXN * W];
__device__ __half g_aggh[MAXN * W];
__device__ __half g_h1h[MAXN * W];
__device__ __half g_wh[2 * 128 * 256];   // combined [Wrel|Wroot] fp16, per conv
__device__ float g_sum[G * W];
__device__ float g_sumsq[G * W];
__device__ float g_alpha[G * W];
__device__ float g_beta[G * W];
__device__ float g_cnt[G];
__device__ int   g_deg[MAXN];
__device__ int   g_base[MAXN + 4];
__device__ int   g_cur[MAXN];
__device__ int2  g_elist[MAXE];
__device__ int   g_bsum[64];

// ---------------- PTX helpers (sm_80/90 baseline only) -----------------------
__device__ __forceinline__ uint32_t smem_u32(const void* p) {
    uint32_t a;
    asm("{ .reg .u64 t; cvta.to.shared.u64 t, %1; cvt.u32.u64 %0, t; }"
        : "=r"(a) : "l"(p));
    return a;
}
__device__ __forceinline__ void ldsm4(uint4& r, uint32_t addr) {
    asm volatile("ldmatrix.sync.aligned.m8n8.x4.shared.b16 {%0,%1,%2,%3}, [%4];"
                 : "=r"(r.x), "=r"(r.y), "=r"(r.z), "=r"(r.w) : "r"(addr));
}
__device__ __forceinline__ void mma16816(float* d, const uint4& a,
                                         uint32_t b0, uint32_t b1) {
    asm volatile(
        "mma.sync.aligned.m16n8k16.row.col.f32.f16.f16.f32 "
        "{%0,%1,%2,%3}, {%4,%5,%6,%7}, {%8,%9}, {%0,%1,%2,%3};"
        : "+f"(d[0]), "+f"(d[1]), "+f"(d[2]), "+f"(d[3])
        : "r"(a.x), "r"(a.y), "r"(a.z), "r"(a.w), "r"(b0), "r"(b1));
}

// ---------------- 1. per-graph stats (batch_map is sorted) ------------------
__global__ __launch_bounds__(128) void stats_kernel(
    const float* __restrict__ x, const int* __restrict__ bmap, int n, int chunk)
{
    int n0 = blockIdx.x * chunk;
    if (n0 >= n) return;
    int n1 = min(n0 + chunk, n);
    int f = threadIdx.x;

    float s = 0.f, ss = 0.f;
    int curg = bmap[n0];
    int runStart = n0;
    for (int r = n0; r < n1; r++) {
        int g = bmap[r];
        if (g != curg) {
            atomicAdd(&g_sum[curg * W + f], s);
            atomicAdd(&g_sumsq[curg * W + f], ss);
            if (f == 0) atomicAdd(&g_cnt[curg], (float)(r - runStart));
            s = 0.f; ss = 0.f; curg = g; runStart = r;
        }
        float v = x[(size_t)r * W + f];
        s += v; ss += v * v;
    }
    atomicAdd(&g_sum[curg * W + f], s);
    atomicAdd(&g_sumsq[curg * W + f], ss);
    if (f == 0) atomicAdd(&g_cnt[curg], (float)(n1 - runStart));
}

// ---------------- 2. finalize per-(graph,feature) affine --------------------
__global__ __launch_bounds__(128) void finalize_kernel(
    const float* __restrict__ gnw, const float* __restrict__ gnb,
    const float* __restrict__ msc)
{
    int g = blockIdx.x, f = threadIdx.x;
    float cnt  = g_cnt[g];
    float inv  = (cnt > 0.f) ? (1.f / cnt) : 0.f;
    float mean = g_sum[g * W + f] * inv;
    float q    = g_sumsq[g * W + f] * inv;
    float m    = msc[f];
    float var  = q - mean * mean * m * (2.f - m);
    float istd = rsqrtf(var + EPS);
    float a    = gnw[f] * istd;
    g_alpha[g * W + f] = a;
    g_beta[g * W + f]  = gnb[f] - a * m * mean;
}

// ---------------- 2b. weight prep: fp32 [Wrel|Wroot] -> fp16 combined --------
__global__ __launch_bounds__(128) void wprep_kernel(
    const float* __restrict__ Wr1, const float* __restrict__ Wo1,
    const float* __restrict__ Wr2, const float* __restrict__ Wo2)
{
    int conv = blockIdx.y, row = blockIdx.x, t = threadIdx.x;   // t < 128
    const float* Wr = conv ? Wr2 : Wr1;
    const float* Wo = conv ? Wo2 : Wo1;
    const float* s = (t < 64) ? (Wr + row * 128 + t * 2)
                              : (Wo + row * 128 + (t - 64) * 2);
    float2 v = *(const float2*)s;
    __half2* dst = (__half2*)(g_wh + (size_t)conv * 128 * 256 + row * 256) + t;
    *dst = __floats2half2_rn(v.x, v.y);
}

// ---------------- 3. normalize -> fp16 ---------------------------------------
__global__ __launch_bounds__(256) void norm_kernel(
    const float4* __restrict__ x, const int* __restrict__ bmap, int total)
{
    int idx = blockIdx.x * 256 + threadIdx.x;
    if (idx >= total) return;
    int r = idx >> 5, c = idx & 31;
    int g = __ldg(bmap + r);
    float4 xv = __ldg(x + idx);
    float4 a = ((const float4*)g_alpha)[g * 32 + c];
    float4 b = ((const float4*)g_beta)[g * 32 + c];
    float ox = fmaf(a.x, xv.x, b.x);
    float oy = fmaf(a.y, xv.y, b.y);
    float oz = fmaf(a.z, xv.z, b.z);
    float ow = fmaf(a.w, xv.w, b.w);
    uint2 o;
    *(__half2*)&o.x = __floats2half2_rn(ox, oy);
    *(__half2*)&o.y = __floats2half2_rn(oz, ow);
    ((uint2*)g_xnh)[idx] = o;
}

// ---------------- CSR build: hist -> scan1/2/3 -> place ----------------------
__global__ __launch_bounds__(256) void hist_kernel(const int* __restrict__ dst, int E)
{
    int e = blockIdx.x * 256 + threadIdx.x;
    if (e < E) atomicAdd(&g_deg[dst[e]], 1);
}

__global__ __launch_bounds__(256) void scan1_kernel(int n4)
{
    __shared__ int wS[8];
    int b = blockIdx.x, tid = threadIdx.x, lane = tid & 31, wid = tid >> 5;
    const int4* dp = (const int4*)g_deg;
    int i4 = b * 1024 + tid * 4;
    int s = 0;
    #pragma unroll
    for (int j = 0; j < 4; j++) {
        if (i4 + j < n4) {
            int4 v = dp[i4 + j];
            s += v.x + v.y + v.z + v.w;
        }
    }
    #pragma unroll
    for (int o = 16; o > 0; o >>= 1) s += __shfl_down_sync(~0u, s, o);
    if (lane == 0) wS[wid] = s;
    __syncthreads();
    if (tid == 0) {
        int t = 0;
        #pragma unroll
        for (int k = 0; k < 8; k++) t += wS[k];
        g_bsum[b] = t;
    }
}

__global__ void scan2_kernel(int nb, int n)
{
    if (threadIdx.x == 0) {
        int run = 0;
        for (int i = 0; i < nb; i++) {
            int t = g_bsum[i];
            g_bsum[i] = run;
            run += t;
        }
        g_base[n] = run;
    }
}

__global__ __launch_bounds__(256) void scan3_kernel(int n4)
{
    __shared__ int wS[8];
    int b = blockIdx.x, tid = threadIdx.x, lane = tid & 31, wid = tid >> 5;
    const int4* dp = (const int4*)g_deg;
    int i4 = b * 1024 + tid * 4;
    int4 v[4];
    int s = 0;
    #pragma unroll
    for (int j = 0; j < 4; j++) {
        v[j] = make_int4(0, 0, 0, 0);
        if (i4 + j < n4) v[j] = dp[i4 + j];
        s += v[j].x + v[j].y + v[j].z + v[j].w;
    }
    int x = s;
    #pragma unroll
    for (int o = 1; o < 32; o <<= 1) {
        int y = __shfl_up_sync(~0u, x, o);
        if (lane >= o) x += y;
    }
    if (lane == 31) wS[wid] = x;
    __syncthreads();
    int woff = 0;
    #pragma unroll
    for (int k = 0; k < 8; k++)
        if (k < wid) woff += wS[k];
    int run = g_bsum[b] + woff + x - s;
    int4* bp = (int4*)g_base;
    #pragma unroll
    for (int j = 0; j < 4; j++) {
        if (i4 + j < n4) {
            int4 o;
            o.x = run; run += v[j].x;
            o.y = run; run += v[j].y;
            o.z = run; run += v[j].z;
            o.w = run; run += v[j].w;
            bp[i4 + j] = o;
        }
    }
}

__global__ __launch_bounds__(256) void place_kernel(
    const int* __restrict__ src, const int* __restrict__ dst,
    const float* __restrict__ ew, int E)
{
    int e = blockIdx.x * 256 + threadIdx.x;
    if (e >= E) return;
    int d = dst[e];
    int p = g_base[d] + atomicAdd(&g_cur[d], 1);
    g_elist[p] = make_int2(src[e], __float_as_int(ew[e]));
}

// ---------------- gather (fp16 rows, fp32 accumulate) ------------------------
__global__ __launch_bounds__(256) void gather_kernel(
    const uint2* __restrict__ in, uint2* __restrict__ agg, int n)
{
    int warp = (blockIdx.x * 256 + threadIdx.x) >> 5;
    if (warp >= n) return;
    int c = threadIdx.x & 31;
    int b0 = g_base[warp], b1 = g_base[warp + 1];
    float4 acc = make_float4(0.f, 0.f, 0.f, 0.f);
    int e = b0;
    #pragma unroll 1
    for (; e + 2 <= b1; e += 2) {
        int2 s0 = __ldg(&g_elist[e]);
        int2 s1 = __ldg(&g_elist[e + 1]);
        uint2 v0 = __ldg(in + (size_t)s0.x * 32 + c);
        uint2 v1 = __ldg(in + (size_t)s1.x * 32 + c);
        float w0 = __int_as_float(s0.y), w1 = __int_as_float(s1.y);
        float2 a0 = __half22float2(*(__half2*)&v0.x);
        float2 a1 = __half22float2(*(__half2*)&v0.y);
        acc.x = fmaf(w0, a0.x, acc.x); acc.y = fmaf(w0, a0.y, acc.y);
        acc.z = fmaf(w0, a1.x, acc.z); acc.w = fmaf(w0, a1.y, acc.w);
        float2 b0f = __half22float2(*(__half2*)&v1.x);
        float2 b1f = __half22float2(*(__half2*)&v1.y);
        acc.x = fmaf(w1, b0f.x, acc.x); acc.y = fmaf(w1, b0f.y, acc.y);
        acc.z = fmaf(w1, b1f.x, acc.z); acc.w = fmaf(w1, b1f.y, acc.w);
    }
    if (e < b1) {
        int2 s0 = __ldg(&g_elist[e]);
        uint2 v0 = __ldg(in + (size_t)s0.x * 32 + c);
        float w0 = __int_as_float(s0.y);
        float2 a0 = __half22float2(*(__half2*)&v0.x);
        float2 a1 = __half22float2(*(__half2*)&v0.y);
        acc.x = fmaf(w0, a0.x, acc.x); acc.y = fmaf(w0, a0.y, acc.y);
        acc.z = fmaf(w0, a1.x, acc.z); acc.w = fmaf(w0, a1.y, acc.w);
    }
    uint2 o;
    *(__half2*)&o.x = __floats2half2_rn(acc.x, acc.y);
    *(__half2*)&o.y = __floats2half2_rn(acc.z, acc.w);
    agg[(size_t)warp * 32 + c] = o;
}

// ---------------- fp16 warp-MMA GEMM: out = epi([A|B]@[Wrel;Wroot]^T) -------
// A (fp16): 4 chunks of k=64 (c<2: agg, c>=2: root input), double-buffered,
//   smem rows 128B, swizzle u^(row&7). Weights: 128 n-rows x 512B (K=256)
//   staged once, swizzle on low-3 16B units. mma.m16n8k16.f16, fp32 accum.
// MODE 0: LeakyReLU -> fp16 h1    MODE 1: + residual -> fp32 out
#define GH_A0   1024
#define GH_A1   (GH_A0 + 16384)
#define GH_WS   (GH_A1 + 16384)
#define GH_SMEM (GH_WS + 65536)

__device__ __forceinline__ void ldgAh(uint4* regs, int tid, int r0, int n, int c,
                                      const __half* __restrict__ Arel,
                                      const __half* __restrict__ Aroot)
{
    const __half* As = (c < 2) ? Arel : Aroot;
    int ub = (c & 1) * 8;
    #pragma unroll
    for (int i = 0; i < 4; i++) {
        int q = tid + i * 256;
        int row = q >> 3, u = q & 7;
        int gr = r0 + row;
        regs[i] = make_uint4(0u, 0u, 0u, 0u);
        if (gr < n) regs[i] = __ldg((const uint4*)As + (size_t)gr * 16 + ub + u);
    }
}
__device__ __forceinline__ void stsAh(const uint4* regs, char* sa, int tid)
{
    #pragma unroll
    for (int i = 0; i < 4; i++) {
        int q = tid + i * 256;
        int row = q >> 3, u = q & 7;
        *(uint4*)(sa + row * 128 + ((u ^ (row & 7)) << 4)) = regs[i];
    }
}

template <int MODE>
__global__ __launch_bounds__(256) void gemm_h_kernel(
    const __half* __restrict__ Arel, const __half* __restrict__ Aroot,
    const __half* __restrict__ wh, const float* __restrict__ brel,
    const float* __restrict__ resid, void* __restrict__ outv, int n)
{
    extern __shared__ char smem[];
    uint32_t sbase = smem_u32(smem);
    int tid = threadIdx.x, wid = tid >> 5, lane = tid & 31;
    int wm = wid & 3, wn = wid >> 2;
    int r0 = blockIdx.x * 128;

    if (tid < 128) ((float*)smem)[tid] = __ldg(brel + tid);

    // stage all weights (fp16, swizzled): 128 rows x 32 units
    #pragma unroll
    for (int i = 0; i < 16; i++) {
        int q = tid + i * 256;
        int row = q >> 5, uu = q & 31;
        uint4 v = __ldg((const uint4*)wh + (size_t)row * 32 + uu);
        int phys = (uu & 0x18) | ((uu ^ row) & 7);
        *(uint4*)(smem + GH_WS + row * 512 + phys * 16) = v;
    }

    float acc[2][8][4];
    #pragma unroll
    for (int t = 0; t < 2; t++)
        #pragma unroll
        for (int u = 0; u < 8; u++)
            #pragma unroll
            for (int v = 0; v < 4; v++) acc[t][u][v] = 0.f;

    int j = lane & 7, grp = lane >> 3;
    int a_row = wm * 32 + ((grp & 1) << 3) + j;   // + t*16
    int a_r7  = a_row & 7;
    int a_ub  = grp >> 1;                          // + ks*2
    int b_row = wn * 64 + (((grp >> 1) & 1) << 3) + j;  // + p*16
    int b_r7  = b_row & 7;
    int b_ub  = grp & 1;                           // + ks*2 + c*8

    uint4 ar[4];
    ldgAh(ar, tid, r0, n, 0, Arel, Aroot);
    stsAh(ar, smem + GH_A0, tid);

    #pragma unroll 1
    for (int c = 0; c < 4; c++) {
        if (c < 3) ldgAh(ar, tid, r0, n, c + 1, Arel, Aroot);
        __syncthreads();
        uint32_t aB = sbase + ((c & 1) ? GH_A1 : GH_A0);
        uint32_t bB = sbase + GH_WS;
        #pragma unroll
        for (int ks = 0; ks < 4; ks++) {
            uint4 af[2];
            #pragma unroll
            for (int t = 0; t < 2; t++) {
                int row = a_row + t * 16;
                int u = ks * 2 + a_ub;
                ldsm4(af[t], aB + row * 128 + (((u ^ a_r7) & 7) << 4));
            }
            uint4 bf[4];
            #pragma unroll
            for (int p = 0; p < 4; p++) {
                int row = b_row + p * 16;
                int uu = c * 8 + ks * 2 + b_ub;
                int phys = (uu & 0x18) | ((uu ^ b_r7) & 7);
                ldsm4(bf[p], bB + row * 512 + phys * 16);
            }
            #pragma unroll
            for (int t = 0; t < 2; t++)
                #pragma unroll
                for (int u = 0; u < 8; u++) {
                    int p = u >> 1;
                    uint32_t b0 = (u & 1) ? bf[p].z : bf[p].x;
                    uint32_t b1 = (u & 1) ? bf[p].w : bf[p].y;
                    mma16816(acc[t][u], af[t], b0, b1);
                }
        }
        if (c < 3)
            stsAh(ar, smem + (((c + 1) & 1) ? GH_A1 : GH_A0), tid);
    }

    // epilogue
    const float* bias = (const float*)smem;
    int rb = r0 + wm * 32 + (lane >> 2);
    int cb = wn * 64 + ((lane & 3) << 1);
    #pragma unroll
    for (int t = 0; t < 2; t++) {
        #pragma unroll
        for (int u = 0; u < 8; u++) {
            int cc = cb + u * 8;
            float b0v = bias[cc], b1v = bias[cc + 1];
            #pragma unroll
            for (int h = 0; h < 2; h++) {
                int r = rb + t * 16 + h * 8;
                if (r >= n) continue;
                float vx = acc[t][u][h * 2 + 0] + b0v;
                float vy = acc[t][u][h * 2 + 1] + b1v;
                if (MODE == 0) {
                    vx = (vx >= 0.f) ? vx : 0.1f * vx;
                    vy = (vy >= 0.f) ? vy : 0.1f * vy;
                    __half2* op = (__half2*)((__half*)outv + (size_t)r * W + cc);
                    *op = __floats2half2_rn(vx, vy);
                } else {
                    float2 rr = *(const float2*)(resid + (size_t)r * W + cc);
                    vx += rr.x; vy += rr.y;
                    *(float2*)((float*)outv + (size_t)r * W + cc) =
                        make_float2(vx, vy);
                }
            }
        }
    }
}

// ---------------- launch -----------------------------------------------------
extern "C" void kernel_launch(void* const* d_in, const int* in_sizes, int n_in,
                              void* d_out, int out_size)
{
    const float* x      = (const float*)d_in[0];
    const int*   eidx   = (const int*)d_in[1];
    const float* ew     = (const float*)d_in[2];
    const int*   bmap   = (const int*)d_in[3];
    const float* gnw    = (const float*)d_in[4];
    const float* gnb    = (const float*)d_in[5];
    const float* msc    = (const float*)d_in[6];
    const float* Wrel1  = (const float*)d_in[7];
    const float* brel1  = (const float*)d_in[8];
    const float* Wroot1 = (const float*)d_in[9];
    const float* Wrel2  = (const float*)d_in[10];
    const float* brel2  = (const float*)d_in[11];
    const float* Wroot2 = (const float*)d_in[12];
    float* out = (float*)d_out;

    int n = in_sizes[0] / W;
    int E = in_sizes[2];
    const int* src = eidx;
    const int* dst = eidx + E;

    void *p_sum, *p_sumsq, *p_cnt, *p_xnh, *p_aggh, *p_h1h, *p_deg, *p_cur, *p_wh;
    cudaGetSymbolAddress(&p_sum, g_sum);
    cudaGetSymbolAddress(&p_sumsq, g_sumsq);
    cudaGetSymbolAddress(&p_cnt, g_cnt);
    cudaGetSymbolAddress(&p_xnh, g_xnh);
    cudaGetSymbolAddress(&p_aggh, g_aggh);
    cudaGetSymbolAddress(&p_h1h, g_h1h);
    cudaGetSymbolAddress(&p_deg, g_deg);
    cudaGetSymbolAddress(&p_cur, g_cur);
    cudaGetSymbolAddress(&p_wh, g_wh);
    __half* xnh  = (__half*)p_xnh;
    __half* aggh = (__half*)p_aggh;
    __half* h1h  = (__half*)p_h1h;
    __half* wh   = (__half*)p_wh;

    cudaFuncSetAttribute(gemm_h_kernel<0>,
                         cudaFuncAttributeMaxDynamicSharedMemorySize, GH_SMEM);
    cudaFuncSetAttribute(gemm_h_kernel<1>,
                         cudaFuncAttributeMaxDynamicSharedMemorySize, GH_SMEM);

    cudaMemsetAsync(p_sum,   0, G * W * sizeof(float), 0);
    cudaMemsetAsync(p_sumsq, 0, G * W * sizeof(float), 0);
    cudaMemsetAsync(p_cnt,   0, G * sizeof(float), 0);
    cudaMemsetAsync(p_deg,   0, (size_t)n * sizeof(int), 0);
    cudaMemsetAsync(p_cur,   0, (size_t)n * sizeof(int), 0);

    // GraphNorm stats + affine; weight fp16 prep
    const int CHUNK = 256;
    stats_kernel<<<(n + CHUNK - 1) / CHUNK, 128>>>(x, bmap, n, CHUNK);
    finalize_kernel<<<G, 128>>>(gnw, gnb, msc);
    wprep_kernel<<<dim3(128, 2), 128>>>(Wrel1, Wroot1, Wrel2, Wroot2);

    // CSR build (shared by both convs)
    int n4 = (n + 3) / 4;
    int nscan = (n4 + 1023) / 1024;
    hist_kernel<<<(E + 255) / 256, 256>>>(dst, E);
    scan1_kernel<<<nscan, 256>>>(n4);
    scan2_kernel<<<1, 32>>>(nscan, n);
    scan3_kernel<<<nscan, 256>>>(n4);
    place_kernel<<<(E + 255) / 256, 256>>>(src, dst, ew, E);

    // normalize -> fp16
    int total4 = n * 32;
    norm_kernel<<<(total4 + 255) / 256, 256>>>((const float4*)x, bmap, total4);

    // conv1: gather + GEMM(+LeakyReLU) -> fp16 h1
    int gwBlocks = (n * 32 + 255) / 256;
    gather_kernel<<<gwBlocks, 256>>>((const uint2*)xnh, (uint2*)aggh, n);
    int gBlocks = (n + 127) / 128;
    gemm_h_kernel<0><<<gBlocks, 256, GH_SMEM>>>(
        aggh, xnh, wh, brel1, nullptr, h1h, n);

    // conv2: gather + GEMM(+residual) -> fp32 out
    gather_kernel<<<gwBlocks, 256>>>((const uint2*)h1h, (uint2*)aggh, n);
    gemm_h_kernel<1><<<gBlocks, 256, GH_SMEM>>>(
        aggh, h1h, wh + 128 * 256, brel2, x, out, n);
}